// round 1
// baseline (speedup 1.0000x reference)
#include <cuda_runtime.h>
#include <math.h>
#include <stdint.h>

#define B_ROWS 65536
#define D1V 64
#define D2V 64
#define DCV 128
#define KBINS 8
#define DFF 1024
#define NPP 23          // 3*K - 1
#define DIN 256         // 2*D1 + DC
#define NOUT (NPP*D2V)  // 1472

// ---------------- scratch (static device globals: allocation-guard safe) ----
__device__ float g_in[(size_t)B_ROWS * DIN];       //  64 MB
__device__ float g_h0[(size_t)B_ROWS * DFF];       // 256 MB
__device__ float g_h1[(size_t)B_ROWS * DFF];       // 256 MB
__device__ float g_params[(size_t)B_ROWS * NOUT];  // 385 MB

// ---------------- concat(x1, mask1, context) -> g_in ------------------------
__global__ void concat_kernel(const float* __restrict__ x1,
                              const float* __restrict__ mask1,
                              const float* __restrict__ ctx) {
    int i = blockIdx.x * 256 + threadIdx.x;
    int b = i >> 8;
    int j = i & 255;
    float v;
    if (j < 64)       v = x1[b * 64 + j];
    else if (j < 128) v = mask1[b * 64 + (j - 64)];
    else              v = ctx[b * 128 + (j - 128)];
    g_in[i] = v;
}

// ---------------- fp32 tiled GEMM: C = act(A @ W + bias) --------------------
// A: [M,K] row-major, W: [K,N] row-major, C: [M,N].
// Block tile 128x64, BK=16, 256 threads, 8x4 per-thread microtile.
template <bool RELU>
__global__ __launch_bounds__(256)
void gemm_kernel(const float* __restrict__ A, const float* __restrict__ W,
                 const float* __restrict__ bias, float* __restrict__ C,
                 int N, int K) {
    const int BM = 128, BN = 64, BK = 16, ASTR = 132;  // pad to dodge STS conflicts
    __shared__ float As[BK * ASTR];
    __shared__ float Bs[BK * BN];

    int tid = threadIdx.x;
    int tx = tid & 15;   // 0..15 -> col group (4 cols)
    int ty = tid >> 4;   // 0..15 -> row group (8 rows)
    size_t row0 = (size_t)blockIdx.y * BM;
    int col0 = blockIdx.x * BN;

    float acc[8][4];
#pragma unroll
    for (int i = 0; i < 8; i++)
#pragma unroll
        for (int j = 0; j < 4; j++) acc[i][j] = 0.0f;

    const float* Ab = A + row0 * (size_t)K;

    for (int kt = 0; kt < K; kt += BK) {
        // load A tile (128x16): 512 float4, 2 per thread; store transposed
#pragma unroll
        for (int t = 0; t < 2; t++) {
            int i = tid + t * 256;        // 0..511
            int m = i >> 2;               // 0..127
            int kk = (i & 3) * 4;         // 0,4,8,12
            float4 v = *(const float4*)(Ab + (size_t)m * K + kt + kk);
            As[(kk + 0) * ASTR + m] = v.x;
            As[(kk + 1) * ASTR + m] = v.y;
            As[(kk + 2) * ASTR + m] = v.z;
            As[(kk + 3) * ASTR + m] = v.w;
        }
        // load W tile (16x64): 1 float4 per thread
        {
            int k = tid >> 4;             // 0..15
            int n = (tid & 15) * 4;       // 0..60
            *(float4*)&Bs[k * BN + n] =
                *(const float4*)(W + (size_t)(kt + k) * N + col0 + n);
        }
        __syncthreads();

#pragma unroll
        for (int k = 0; k < BK; k++) {
            float4 a0 = *(float4*)&As[k * ASTR + ty * 8];
            float4 a1 = *(float4*)&As[k * ASTR + ty * 8 + 4];
            float4 bv = *(float4*)&Bs[k * BN + tx * 4];
            float a[8] = {a0.x, a0.y, a0.z, a0.w, a1.x, a1.y, a1.z, a1.w};
            float bb[4] = {bv.x, bv.y, bv.z, bv.w};
#pragma unroll
            for (int i = 0; i < 8; i++)
#pragma unroll
                for (int j = 0; j < 4; j++) acc[i][j] += a[i] * bb[j];
        }
        __syncthreads();
    }

    float4 bias4 = *(const float4*)(bias + col0 + tx * 4);
#pragma unroll
    for (int i = 0; i < 8; i++) {
        float4 o;
        o.x = acc[i][0] + bias4.x;
        o.y = acc[i][1] + bias4.y;
        o.z = acc[i][2] + bias4.z;
        o.w = acc[i][3] + bias4.w;
        if (RELU) {
            o.x = fmaxf(o.x, 0.0f); o.y = fmaxf(o.y, 0.0f);
            o.z = fmaxf(o.z, 0.0f); o.w = fmaxf(o.w, 0.0f);
        }
        *(float4*)(C + (row0 + ty * 8 + i) * (size_t)N + col0 + tx * 4) = o;
    }
}

// ---------------- rational-quadratic spline + reductions --------------------
// jax softplus: max(x,0) + log1p(exp(-|x|))
__device__ __forceinline__ float softplus_f(float x) {
    return fmaxf(x, 0.0f) + log1pf(expf(-fabsf(x)));
}

__global__ void spline_kernel(const float* __restrict__ x2g,
                              float* __restrict__ out) {
    const float SHIFT    = 0.5413248546129181f;   // log(e-1)
    const float SHIFT_DX = 5.1944681678044580f;   // log(exp(6-0.8)-1)
    __shared__ float red[4][2];

    int d = threadIdx.x;                          // 0..63
    int b = blockIdx.x * blockDim.y + threadIdx.y;

    const float* p = g_params + (size_t)b * NOUT + d * NPP;
    float pr[NPP];
#pragma unroll
    for (int i = 0; i < NPP; i++) pr[i] = p[i];

    // constants derived exactly as the reference computes them (f32 ops)
    const float left = -3.0f;
    float dx = 0.8f + softplus_f(SHIFT_DX);       // ~= 6.0
    float right = left + dx;
    float scale = right - left;

    // ---- softmax(w_raw) -> scaled cumsum -> cw[0..8]
    float cw[KBINS + 1], ch[KBINS + 1], dv[KBINS + 1];
    {
        float m = pr[0];
#pragma unroll
        for (int i = 1; i < KBINS; i++) m = fmaxf(m, pr[i]);
        float e[KBINS]; float s = 0.0f;
#pragma unroll
        for (int i = 0; i < KBINS; i++) { e[i] = expf(pr[i] - m); s += e[i]; }
        float inv = 1.0f / s;
        cw[0] = left;
        float cum = 0.0f;
#pragma unroll
        for (int i = 0; i < KBINS; i++) {
            float w = 0.1f + 0.2f * (e[i] * inv);
            cum += w;
            cw[i + 1] = scale * cum + left;
        }
    }
    // ---- softmax(h_raw) -> ch[0..8]   (bottom=left, top-bottom=scale)
    {
        float m = pr[KBINS];
#pragma unroll
        for (int i = 1; i < KBINS; i++) m = fmaxf(m, pr[KBINS + i]);
        float e[KBINS]; float s = 0.0f;
#pragma unroll
        for (int i = 0; i < KBINS; i++) { e[i] = expf(pr[KBINS + i] - m); s += e[i]; }
        float inv = 1.0f / s;
        ch[0] = left;
        float cum = 0.0f;
#pragma unroll
        for (int i = 0; i < KBINS; i++) {
            float w = 0.1f + 0.2f * (e[i] * inv);
            cum += w;
            ch[i + 1] = scale * cum + left;
        }
    }
    // ---- derivatives: [1, softplus-shifted x7, 1]
    dv[0] = 1.0f;
#pragma unroll
    for (int i = 0; i < 7; i++) dv[i + 1] = 0.001f + softplus_f(pr[16 + i] + SHIFT);
    dv[KBINS] = 1.0f;

    float x = x2g[(size_t)b * D2V + d];

    // ---- bin index: sum(bumped <= x) - 1, clipped to [0,7]
    int cnt = 0;
#pragma unroll
    for (int j = 0; j < KBINS; j++) cnt += (cw[j] <= x) ? 1 : 0;
    cnt += ((cw[KBINS] + 1e-6f) <= x) ? 1 : 0;
    int idx = cnt - 1;
    idx = idx < 0 ? 0 : (idx > KBINS - 1 ? KBINS - 1 : idx);

    // ---- gather via unrolled compare-select (keeps arrays in registers)
    float x_k = cw[0], x_k1 = cw[1], y_k = ch[0], y_k1 = ch[1];
    float d0 = dv[0], dv1 = dv[1];
#pragma unroll
    for (int j = 0; j < KBINS; j++) {
        if (j == idx) {
            x_k = cw[j]; x_k1 = cw[j + 1];
            y_k = ch[j]; y_k1 = ch[j + 1];
            d0 = dv[j];  dv1 = dv[j + 1];
        }
    }
    float x_kd = x_k1 - x_k;
    float y_kd = y_k1 - y_k;
    float s_k = y_kd / x_kd;

    float xi = (x - x_k) / x_kd;
    float xi1m = xi * (1.0f - xi);
    float omxi = 1.0f - xi;
    float alpha = y_kd * (s_k * xi * xi + d0 * xi1m);
    float beta  = s_k + (dv1 + d0 - 2.0f * s_k) * xi1m;
    float z_sp  = y_k + alpha / fmaxf(beta, 1e-8f);
    float num   = s_k * s_k * (dv1 * xi * xi + 2.0f * s_k * xi1m + d0 * omxi * omxi);
    float ld_sp = logf(fmaxf(num, 1e-8f)) - 2.0f * logf(fmaxf(beta, 1e-8f));

    bool inside = (left <= x) && (x < right);
    float z  = inside ? z_sp : x;       // affine branch: weight=1, bias=0
    float ld = inside ? ld_sp : 0.0f;   // log_weight = 0

    out[(size_t)b * D2V + d] = z;

    // ---- reduce ld over 64 dims (2 warps per row)
#pragma unroll
    for (int off = 16; off > 0; off >>= 1)
        ld += __shfl_down_sync(0xffffffffu, ld, off);
    if ((d & 31) == 0) red[threadIdx.y][d >> 5] = ld;
    __syncthreads();
    if (d == 0)
        out[(size_t)B_ROWS * D2V + b] = red[threadIdx.y][0] + red[threadIdx.y][1];
}

// ---------------- launch -----------------------------------------------------
extern "C" void kernel_launch(void* const* d_in, const int* in_sizes, int n_in,
                              void* d_out, int out_size) {
    const float* x1    = (const float*)d_in[0];
    const float* x2    = (const float*)d_in[1];
    const float* ctx   = (const float*)d_in[2];
    const float* mask1 = (const float*)d_in[3];
    const float* W0    = (const float*)d_in[4];
    const float* b0    = (const float*)d_in[5];
    const float* W1    = (const float*)d_in[6];
    const float* b1    = (const float*)d_in[7];
    const float* W2    = (const float*)d_in[8];
    const float* b2    = (const float*)d_in[9];
    const float* W3    = (const float*)d_in[10];
    const float* b3    = (const float*)d_in[11];
    float* out = (float*)d_out;

    float *pin, *ph0, *ph1, *pp;
    cudaGetSymbolAddress((void**)&pin, g_in);
    cudaGetSymbolAddress((void**)&ph0, g_h0);
    cudaGetSymbolAddress((void**)&ph1, g_h1);
    cudaGetSymbolAddress((void**)&pp,  g_params);

    concat_kernel<<<(B_ROWS * DIN) / 256, 256>>>(x1, mask1, ctx);

    dim3 grid1(DFF / 64, B_ROWS / 128);
    gemm_kernel<true ><<<grid1, 256>>>(pin, W0, b0, ph0, DFF, DIN);
    gemm_kernel<true ><<<grid1, 256>>>(ph0, W1, b1, ph1, DFF, DFF);
    gemm_kernel<true ><<<grid1, 256>>>(ph1, W2, b2, ph0, DFF, DFF);

    dim3 grid3(NOUT / 64, B_ROWS / 128);
    gemm_kernel<false><<<grid3, 256>>>(ph0, W3, b3, pp, NOUT, DFF);

    spline_kernel<<<B_ROWS / 4, dim3(64, 4)>>>(x2, out);
}

// round 3
// speedup vs baseline: 1.9194x; 1.9194x over previous
#include <cuda_runtime.h>
#include <cuda_bf16.h>
#include <math.h>
#include <stdint.h>

#define BR 65536
#define DFF 1024
#define DIN 256
#define NOUT 1472
#define NPAD 1536

typedef __nv_bfloat16 bf16;

// ---------------- static device scratch (allocation-guard safe) -------------
__device__ __align__(256) bf16 gAh[(size_t)BR * DIN];
__device__ __align__(256) bf16 gAl[(size_t)BR * DIN];
__device__ __align__(256) bf16 gH0h[(size_t)BR * DFF];
__device__ __align__(256) bf16 gH0l[(size_t)BR * DFF];
__device__ __align__(256) bf16 gH1h[(size_t)BR * DFF];
__device__ __align__(256) bf16 gH1l[(size_t)BR * DFF];
__device__ __align__(256) bf16 gW0h[DFF * DIN],  gW0l[DFF * DIN];    // [N][K]
__device__ __align__(256) bf16 gW1h[DFF * DFF],  gW1l[DFF * DFF];
__device__ __align__(256) bf16 gW2h[DFF * DFF],  gW2l[DFF * DFF];
__device__ __align__(256) bf16 gW3h[NPAD * DFF], gW3l[NPAD * DFF];
__device__ float gB3p[NPAD];
__device__ __align__(256) float gP[(size_t)BR * NPAD];               // params row-major

// ---------------- helpers ----------------------------------------------------
__device__ __forceinline__ uint32_t smem_u32(const void* p) {
    uint32_t a;
    asm("{ .reg .u64 t; cvta.to.shared.u64 t, %1; cvt.u32.u64 %0, t; }" : "=r"(a) : "l"(p));
    return a;
}
__device__ __forceinline__ void cpasync16(uint32_t dst, const void* src) {
    asm volatile("cp.async.cg.shared.global [%0], [%1], 16;" :: "r"(dst), "l"(src));
}
__device__ __forceinline__ void ldm_x4(uint32_t* r, uint32_t addr) {
    asm volatile("ldmatrix.sync.aligned.m8n8.x4.shared.b16 {%0,%1,%2,%3}, [%4];"
                 : "=r"(r[0]), "=r"(r[1]), "=r"(r[2]), "=r"(r[3]) : "r"(addr));
}
__device__ __forceinline__ void mma_bf16(float* c, const uint32_t* a, uint32_t b0, uint32_t b1) {
    asm volatile("mma.sync.aligned.m16n8k16.row.col.f32.bf16.bf16.f32 "
                 "{%0,%1,%2,%3}, {%4,%5,%6,%7}, {%8,%9}, {%0,%1,%2,%3};"
                 : "+f"(c[0]), "+f"(c[1]), "+f"(c[2]), "+f"(c[3])
                 : "r"(a[0]), "r"(a[1]), "r"(a[2]), "r"(a[3]), "r"(b0), "r"(b1));
}
__device__ __forceinline__ uint32_t pack_bf2(bf16 a, bf16 b) {
    __nv_bfloat162 t(a, b);
    return *reinterpret_cast<uint32_t*>(&t);
}
__device__ __forceinline__ void split_bf(float v, bf16& h, bf16& l) {
    h = __float2bfloat16_rn(v);
    l = __float2bfloat16_rn(v - __bfloat162float(h));
}

// ---------------- concat + split -> Ah/Al [BR][256] row-major ----------------
__global__ void concat_split_kernel(const float* __restrict__ x1,
                                    const float* __restrict__ m1,
                                    const float* __restrict__ cx) {
    int t = blockIdx.x * 256 + threadIdx.x;
    int b = t >> 5;
    int jg = (t & 31) << 3;
    const float* src;
    if (jg < 64)       src = x1 + (size_t)b * 64 + jg;
    else if (jg < 128) src = m1 + (size_t)b * 64 + (jg - 64);
    else               src = cx + (size_t)b * 128 + (jg - 128);
    float4 u0 = *(const float4*)src;
    float4 u1 = *(const float4*)(src + 4);
    float v[8] = {u0.x, u0.y, u0.z, u0.w, u1.x, u1.y, u1.z, u1.w};
    uint32_t ph[4], pl[4];
#pragma unroll
    for (int g = 0; g < 4; g++) {
        bf16 h0, l0, h1, l1;
        split_bf(v[g * 2 + 0], h0, l0);
        split_bf(v[g * 2 + 1], h1, l1);
        ph[g] = pack_bf2(h0, h1);
        pl[g] = pack_bf2(l0, l1);
    }
    size_t o = (size_t)b * DIN + jg;
    *(uint4*)(gAh + o) = make_uint4(ph[0], ph[1], ph[2], ph[3]);
    *(uint4*)(gAl + o) = make_uint4(pl[0], pl[1], pl[2], pl[3]);
}

// ---------------- weight transpose+split: W[K][N] -> Wt hi/lo [Npad][K] ------
__global__ void convert_w_kernel(const float* __restrict__ W,
                                 bf16* __restrict__ hi, bf16* __restrict__ lo,
                                 int K, int N, int Npad) {
    int idx = blockIdx.x * 256 + threadIdx.x;          // (K/8)*Npad threads
    int kg = idx / Npad;
    int n = idx - kg * Npad;
    if (kg >= (K >> 3)) return;
    float v[8];
#pragma unroll
    for (int i = 0; i < 8; i++)
        v[i] = (n < N) ? W[(size_t)(kg * 8 + i) * N + n] : 0.0f;
    uint32_t ph[4], pl[4];
#pragma unroll
    for (int g = 0; g < 4; g++) {
        bf16 h0, l0, h1, l1;
        split_bf(v[g * 2 + 0], h0, l0);
        split_bf(v[g * 2 + 1], h1, l1);
        ph[g] = pack_bf2(h0, h1);
        pl[g] = pack_bf2(l0, l1);
    }
    size_t o = (size_t)n * K + kg * 8;
    *(uint4*)(hi + o) = make_uint4(ph[0], ph[1], ph[2], ph[3]);
    *(uint4*)(lo + o) = make_uint4(pl[0], pl[1], pl[2], pl[3]);
}

__global__ void bias_pad_kernel(const float* __restrict__ b3) {
    int i = blockIdx.x * 256 + threadIdx.x;
    if (i < NPAD) gB3p[i] = (i < NOUT) ? b3[i] : 0.0f;
}

// ---------------- HMMA split-bf16 GEMM ---------------------------------------
// BM=128 BN=128 BK=32, 8 warps (4m x 2n), warp tile 32x64, 4-stage cp.async.
#define SROW 40                       // padded row stride (elems)
#define STG_B 40960                   // stage bytes: 4 * 128*40*2
#define NSTG 4
#define SMEM_GEMM (NSTG * STG_B + 512)

struct StageOff { enum { AH = 0, AL = 10240, BH = 20480, BL = 30720 }; };

__device__ __forceinline__ void load_stage(
    uint32_t sb, int st, int kt, int tid,
    const bf16* Ah, const bf16* Al, const bf16* Bh, const bf16* Bl,
    size_t m0, size_t n0, int K) {
    uint32_t so = sb + st * STG_B;
    int koff = kt * 32;
#pragma unroll
    for (int u = 0; u < 2; u++) {
        int i = tid + u * 256;
        int r = i >> 2;
        int kg = (i & 3) * 8;
        uint32_t d = so + (uint32_t)(r * SROW + kg) * 2;
        size_t ga = (m0 + r) * (size_t)K + koff + kg;
        size_t gb = (n0 + r) * (size_t)K + koff + kg;
        cpasync16(d + StageOff::AH, Ah + ga);
        cpasync16(d + StageOff::AL, Al + ga);
        cpasync16(d + StageOff::BH, Bh + gb);
        cpasync16(d + StageOff::BL, Bl + gb);
    }
    asm volatile("cp.async.commit_group;" ::: "memory");
}

template <bool RELU, bool FINAL>
__global__ __launch_bounds__(256, 1)
void hmma_gemm(const bf16* __restrict__ Ah, const bf16* __restrict__ Al,
               const bf16* __restrict__ Bh, const bf16* __restrict__ Bl,
               const float* __restrict__ bias,
               bf16* __restrict__ Oh, bf16* __restrict__ Ol,
               float* __restrict__ Op, int K, int Nld) {
    extern __shared__ __align__(128) char smem[];
    uint32_t sb = smem_u32(smem);
    float* bsm = (float*)(smem + NSTG * STG_B);

    int tid = threadIdx.x;
    int wid = tid >> 5, lane = tid & 31;
    int wm = wid & 3, wn = wid >> 2;
    size_t m0 = (size_t)blockIdx.y * 128;
    size_t n0 = (size_t)blockIdx.x * 128;
    int KT = K >> 5;

    if (tid < 128) bsm[tid] = bias[n0 + tid];

    float acc[2][8][4];
#pragma unroll
    for (int mi = 0; mi < 2; mi++)
#pragma unroll
        for (int nj = 0; nj < 8; nj++)
#pragma unroll
            for (int q = 0; q < 4; q++) acc[mi][nj][q] = 0.0f;

    // ldmatrix per-lane base offsets (within a stage)
    int lrow = lane & 15;
    int lcol = (lane >> 4) * 8;
    uint32_t aBase = (uint32_t)((wm * 32 + lrow) * SROW + lcol) * 2;
    uint32_t bBase = (uint32_t)((wn * 64 + lrow) * SROW + lcol) * 2;

    // prologue: fill 3 stages
#pragma unroll
    for (int s = 0; s < NSTG - 1; s++)
        load_stage(sb, s, s, tid, Ah, Al, Bh, Bl, m0, n0, K);

#pragma unroll 1
    for (int kt = 0; kt < KT; kt++) {
        asm volatile("cp.async.wait_group 2;" ::: "memory");
        __syncthreads();
        uint32_t so = sb + (kt & (NSTG - 1)) * STG_B;
#pragma unroll
        for (int k16 = 0; k16 < 2; k16++) {
            uint32_t kb = (uint32_t)(k16 * 16) * 2;
            uint32_t ahf[2][4], alf[2][4];
#pragma unroll
            for (int mi = 0; mi < 2; mi++) {
                uint32_t ao = so + aBase + (uint32_t)(mi * 16 * SROW) * 2 + kb;
                ldm_x4(ahf[mi], ao + StageOff::AH);
                ldm_x4(alf[mi], ao + StageOff::AL);
            }
#pragma unroll
            for (int nj = 0; nj < 4; nj++) {
                uint32_t bo = so + bBase + (uint32_t)(nj * 16 * SROW) * 2 + kb;
                uint32_t bh[4], bl[4];
                ldm_x4(bh, bo + StageOff::BH);
                ldm_x4(bl, bo + StageOff::BL);
#pragma unroll
                for (int mi = 0; mi < 2; mi++) {
                    float* c0 = acc[mi][nj * 2 + 0];
                    float* c1 = acc[mi][nj * 2 + 1];
                    mma_bf16(c0, ahf[mi], bh[0], bh[2]);
                    mma_bf16(c0, alf[mi], bh[0], bh[2]);
                    mma_bf16(c0, ahf[mi], bl[0], bl[2]);
                    mma_bf16(c1, ahf[mi], bh[1], bh[3]);
                    mma_bf16(c1, alf[mi], bh[1], bh[3]);
                    mma_bf16(c1, ahf[mi], bl[1], bl[3]);
                }
            }
        }
        __syncthreads();
        int nk = kt + NSTG - 1;
        if (nk < KT)
            load_stage(sb, nk & (NSTG - 1), nk, tid, Ah, Al, Bh, Bl, m0, n0, K);
        else
            asm volatile("cp.async.commit_group;" ::: "memory");
    }

    // ---- epilogue ----
    int qrow = lane >> 2, qcol = (lane & 3) * 2;
#pragma unroll
    for (int mi = 0; mi < 2; mi++) {
#pragma unroll
        for (int nj = 0; nj < 8; nj++) {
            float* c = acc[mi][nj];
            int col = wn * 64 + nj * 8 + qcol;
            float bi0 = bsm[col], bi1 = bsm[col + 1];
#pragma unroll
            for (int h = 0; h < 2; h++) {
                size_t row = m0 + wm * 32 + mi * 16 + h * 8 + qrow;
                float v0 = c[h * 2 + 0] + bi0;
                float v1 = c[h * 2 + 1] + bi1;
                if (RELU) { v0 = fmaxf(v0, 0.0f); v1 = fmaxf(v1, 0.0f); }
                size_t o = row * (size_t)Nld + n0 + col;
                if (FINAL) {
                    *(float2*)(Op + o) = make_float2(v0, v1);
                } else {
                    bf16 h0, l0, h1, l1;
                    split_bf(v0, h0, l0);
                    split_bf(v1, h1, l1);
                    *(uint32_t*)(Oh + o) = pack_bf2(h0, h1);
                    *(uint32_t*)(Ol + o) = pack_bf2(l0, l1);
                }
            }
        }
    }
}

// ---------------- rational-quadratic spline ----------------------------------
__device__ __forceinline__ float softplus_f(float x) {
    return fmaxf(x, 0.0f) + log1pf(expf(-fabsf(x)));
}

__global__ void spline_kernel(const float* __restrict__ x2g,
                              float* __restrict__ out) {
    const float SHIFT    = 0.5413248546129181f;   // log(e-1)
    const float SHIFT_DX = 5.1944681678044580f;   // log(exp(6-0.8)-1)
    __shared__ float red[4][2];

    int d = threadIdx.x;                          // 0..63
    int b = blockIdx.x * blockDim.y + threadIdx.y;

    const float* p = gP + (size_t)b * NPAD + d * 23;
    float pr[23];
#pragma unroll
    for (int i = 0; i < 23; i++) pr[i] = p[i];

    const float left = -3.0f;
    float dx = 0.8f + softplus_f(SHIFT_DX);
    float right = left + dx;
    float scale = right - left;

    float cw[9], ch[9], dv[9];
    {
        float m = pr[0];
#pragma unroll
        for (int i = 1; i < 8; i++) m = fmaxf(m, pr[i]);
        float e[8]; float s = 0.0f;
#pragma unroll
        for (int i = 0; i < 8; i++) { e[i] = expf(pr[i] - m); s += e[i]; }
        float inv = 1.0f / s;
        cw[0] = left;
        float cum = 0.0f;
#pragma unroll
        for (int i = 0; i < 8; i++) {
            cum += 0.1f + 0.2f * (e[i] * inv);
            cw[i + 1] = scale * cum + left;
        }
    }
    {
        float m = pr[8];
#pragma unroll
        for (int i = 1; i < 8; i++) m = fmaxf(m, pr[8 + i]);
        float e[8]; float s = 0.0f;
#pragma unroll
        for (int i = 0; i < 8; i++) { e[i] = expf(pr[8 + i] - m); s += e[i]; }
        float inv = 1.0f / s;
        ch[0] = left;
        float cum = 0.0f;
#pragma unroll
        for (int i = 0; i < 8; i++) {
            cum += 0.1f + 0.2f * (e[i] * inv);
            ch[i + 1] = scale * cum + left;
        }
    }
    dv[0] = 1.0f;
#pragma unroll
    for (int i = 0; i < 7; i++) dv[i + 1] = 0.001f + softplus_f(pr[16 + i] + SHIFT);
    dv[8] = 1.0f;

    float x = x2g[(size_t)b * 64 + d];

    int cnt = 0;
#pragma unroll
    for (int j = 0; j < 8; j++) cnt += (cw[j] <= x) ? 1 : 0;
    cnt += ((cw[8] + 1e-6f) <= x) ? 1 : 0;
    int idx = cnt - 1;
    idx = idx < 0 ? 0 : (idx > 7 ? 7 : idx);

    float x_k = cw[0], x_k1 = cw[1], y_k = ch[0], y_k1 = ch[1];
    float d0 = dv[0], d1 = dv[1];
#pragma unroll
    for (int j = 0; j < 8; j++) {
        if (j == idx) {
            x_k = cw[j]; x_k1 = cw[j + 1];
            y_k = ch[j]; y_k1 = ch[j + 1];
            d0 = dv[j];  d1 = dv[j + 1];
        }
    }
    float x_kd = x_k1 - x_k;
    float y_kd = y_k1 - y_k;
    float s_k = y_kd / x_kd;
    float xi = (x - x_k) / x_kd;
    float xi1m = xi * (1.0f - xi);
    float omxi = 1.0f - xi;
    float alpha = y_kd * (s_k * xi * xi + d0 * xi1m);
    float beta  = s_k + (d1 + d0 - 2.0f * s_k) * xi1m;
    float z_sp  = y_k + alpha / fmaxf(beta, 1e-8f);
    float num   = s_k * s_k * (d1 * xi * xi + 2.0f * s_k * xi1m + d0 * omxi * omxi);
    float ld_sp = logf(fmaxf(num, 1e-8f)) - 2.0f * logf(fmaxf(beta, 1e-8f));

    bool inside = (left <= x) && (x < right);
    float z  = inside ? z_sp : x;
    float ld = inside ? ld_sp : 0.0f;

    out[(size_t)b * 64 + d] = z;

#pragma unroll
    for (int off = 16; off > 0; off >>= 1)
        ld += __shfl_down_sync(0xffffffffu, ld, off);
    if ((d & 31) == 0) red[threadIdx.y][d >> 5] = ld;
    __syncthreads();
    if (d == 0)
        out[(size_t)BR * 64 + b] = red[threadIdx.y][0] + red[threadIdx.y][1];
}

// ---------------- launch -----------------------------------------------------
extern "C" void kernel_launch(void* const* d_in, const int* in_sizes, int n_in,
                              void* d_out, int out_size) {
    const float* x1    = (const float*)d_in[0];
    const float* x2    = (const float*)d_in[1];
    const float* ctx   = (const float*)d_in[2];
    const float* mask1 = (const float*)d_in[3];
    const float* W0    = (const float*)d_in[4];
    const float* b0    = (const float*)d_in[5];
    const float* W1    = (const float*)d_in[6];
    const float* b1    = (const float*)d_in[7];
    const float* W2    = (const float*)d_in[8];
    const float* b2    = (const float*)d_in[9];
    const float* W3    = (const float*)d_in[10];
    const float* b3    = (const float*)d_in[11];
    float* out = (float*)d_out;

    bf16 *ah, *al, *h0h, *h0l, *h1h, *h1l;
    bf16 *w0h, *w0l, *w1h, *w1l, *w2h, *w2l, *w3h, *w3l;
    float *b3p, *pp;
    cudaGetSymbolAddress((void**)&ah, gAh);   cudaGetSymbolAddress((void**)&al, gAl);
    cudaGetSymbolAddress((void**)&h0h, gH0h); cudaGetSymbolAddress((void**)&h0l, gH0l);
    cudaGetSymbolAddress((void**)&h1h, gH1h); cudaGetSymbolAddress((void**)&h1l, gH1l);
    cudaGetSymbolAddress((void**)&w0h, gW0h); cudaGetSymbolAddress((void**)&w0l, gW0l);
    cudaGetSymbolAddress((void**)&w1h, gW1h); cudaGetSymbolAddress((void**)&w1l, gW1l);
    cudaGetSymbolAddress((void**)&w2h, gW2h); cudaGetSymbolAddress((void**)&w2l, gW2l);
    cudaGetSymbolAddress((void**)&w3h, gW3h); cudaGetSymbolAddress((void**)&w3l, gW3l);
    cudaGetSymbolAddress((void**)&b3p, gB3p); cudaGetSymbolAddress((void**)&pp,  gP);

    cudaFuncSetAttribute(hmma_gemm<true, false>,
                         cudaFuncAttributeMaxDynamicSharedMemorySize, SMEM_GEMM);
    cudaFuncSetAttribute(hmma_gemm<false, true>,
                         cudaFuncAttributeMaxDynamicSharedMemorySize, SMEM_GEMM);

    concat_split_kernel<<<(BR * 32) / 256, 256>>>(x1, mask1, ctx);
    convert_w_kernel<<<((DIN / 8) * DFF) / 256, 256>>>(W0, w0h, w0l, DIN, DFF, DFF);
    convert_w_kernel<<<((DFF / 8) * DFF) / 256, 256>>>(W1, w1h, w1l, DFF, DFF, DFF);
    convert_w_kernel<<<((DFF / 8) * DFF) / 256, 256>>>(W2, w2h, w2l, DFF, DFF, DFF);
    convert_w_kernel<<<((DFF / 8) * NPAD) / 256, 256>>>(W3, w3h, w3l, DFF, NOUT, NPAD);
    bias_pad_kernel<<<(NPAD + 255) / 256, 256>>>(b3);

    dim3 g01(DFF / 128, BR / 128);
    hmma_gemm<true, false><<<g01, 256, SMEM_GEMM>>>(ah, al, w0h, w0l, b0,
                                                    h0h, h0l, nullptr, DIN, DFF);
    hmma_gemm<true, false><<<g01, 256, SMEM_GEMM>>>(h0h, h0l, w1h, w1l, b1,
                                                    h1h, h1l, nullptr, DFF, DFF);
    hmma_gemm<true, false><<<g01, 256, SMEM_GEMM>>>(h1h, h1l, w2h, w2l, b2,
                                                    h0h, h0l, nullptr, DFF, DFF);
    dim3 g3(NPAD / 128, BR / 128);
    hmma_gemm<false, true><<<g3, 256, SMEM_GEMM>>>(h0h, h0l, w3h, w3l, b3p,
                                                   nullptr, nullptr, pp, DFF, NPAD);

    spline_kernel<<<BR / 4, dim3(64, 4)>>>(x2, out);
}

// round 4
// speedup vs baseline: 2.8196x; 1.4690x over previous
#include <cuda_runtime.h>
#include <cuda_fp16.h>
#include <math.h>
#include <stdint.h>

#define BR 65536
#define DFF 1024
#define DIN 256
#define NOUT 1472
#define NPAD 1536

// ---------------- static device scratch (allocation-guard safe) -------------
__device__ __align__(256) __half gA[(size_t)BR * DIN];
__device__ __align__(256) __half gH0[(size_t)BR * DFF];
__device__ __align__(256) __half gH1[(size_t)BR * DFF];
__device__ __align__(256) __half gW0h[DFF * DIN],  gW0l[DFF * DIN];    // [N][K]
__device__ __align__(256) __half gW1h[DFF * DFF],  gW1l[DFF * DFF];
__device__ __align__(256) __half gW2h[DFF * DFF],  gW2l[DFF * DFF];
__device__ __align__(256) __half gW3h[NPAD * DFF], gW3l[NPAD * DFF];
__device__ float gB3p[NPAD];
__device__ __align__(256) float gP[(size_t)BR * NPAD];                 // params row-major

// ---------------- helpers ----------------------------------------------------
__device__ __forceinline__ uint32_t smem_u32(const void* p) {
    uint32_t a;
    asm("{ .reg .u64 t; cvta.to.shared.u64 t, %1; cvt.u32.u64 %0, t; }" : "=r"(a) : "l"(p));
    return a;
}
__device__ __forceinline__ void cpasync16(uint32_t dst, const void* src) {
    asm volatile("cp.async.cg.shared.global [%0], [%1], 16;" :: "r"(dst), "l"(src));
}
__device__ __forceinline__ void ldm_x4(uint32_t* r, uint32_t addr) {
    asm volatile("ldmatrix.sync.aligned.m8n8.x4.shared.b16 {%0,%1,%2,%3}, [%4];"
                 : "=r"(r[0]), "=r"(r[1]), "=r"(r[2]), "=r"(r[3]) : "r"(addr));
}
__device__ __forceinline__ void mma_f16(float* c, const uint32_t* a, uint32_t b0, uint32_t b1) {
    asm volatile("mma.sync.aligned.m16n8k16.row.col.f32.f16.f16.f32 "
                 "{%0,%1,%2,%3}, {%4,%5,%6,%7}, {%8,%9}, {%0,%1,%2,%3};"
                 : "+f"(c[0]), "+f"(c[1]), "+f"(c[2]), "+f"(c[3])
                 : "r"(a[0]), "r"(a[1]), "r"(a[2]), "r"(a[3]), "r"(b0), "r"(b1));
}
__device__ __forceinline__ uint32_t pack_h2(__half a, __half b) {
    __half2 t(a, b);
    return *reinterpret_cast<uint32_t*>(&t);
}
__device__ __forceinline__ void split_h(float v, __half& h, __half& l) {
    h = __float2half_rn(v);
    l = __float2half_rn(v - __half2float(h));
}

// ---------------- concat -> A [BR][256] fp16 ---------------------------------
__global__ void concat_kernel(const float* __restrict__ x1,
                              const float* __restrict__ m1,
                              const float* __restrict__ cx) {
    int t = blockIdx.x * 256 + threadIdx.x;
    int b = t >> 5;
    int jg = (t & 31) << 3;
    const float* src;
    if (jg < 64)       src = x1 + (size_t)b * 64 + jg;
    else if (jg < 128) src = m1 + (size_t)b * 64 + (jg - 64);
    else               src = cx + (size_t)b * 128 + (jg - 128);
    float4 u0 = *(const float4*)src;
    float4 u1 = *(const float4*)(src + 4);
    float v[8] = {u0.x, u0.y, u0.z, u0.w, u1.x, u1.y, u1.z, u1.w};
    uint32_t p[4];
#pragma unroll
    for (int g = 0; g < 4; g++)
        p[g] = pack_h2(__float2half_rn(v[g * 2]), __float2half_rn(v[g * 2 + 1]));
    *(uint4*)(gA + (size_t)b * DIN + jg) = make_uint4(p[0], p[1], p[2], p[3]);
}

// ---------------- weight transpose+split: W[K][N] -> hi/lo [Npad][K] ---------
__global__ void convert_w_kernel(const float* __restrict__ W,
                                 __half* __restrict__ hi, __half* __restrict__ lo,
                                 int K, int N, int Npad) {
    int idx = blockIdx.x * 256 + threadIdx.x;          // (K/8)*Npad threads
    int kg = idx / Npad;
    int n = idx - kg * Npad;
    if (kg >= (K >> 3)) return;
    float v[8];
#pragma unroll
    for (int i = 0; i < 8; i++)
        v[i] = (n < N) ? W[(size_t)(kg * 8 + i) * N + n] : 0.0f;
    uint32_t ph[4], pl[4];
#pragma unroll
    for (int g = 0; g < 4; g++) {
        __half h0, l0, h1, l1;
        split_h(v[g * 2 + 0], h0, l0);
        split_h(v[g * 2 + 1], h1, l1);
        ph[g] = pack_h2(h0, h1);
        pl[g] = pack_h2(l0, l1);
    }
    size_t o = (size_t)n * K + kg * 8;
    *(uint4*)(hi + o) = make_uint4(ph[0], ph[1], ph[2], ph[3]);
    *(uint4*)(lo + o) = make_uint4(pl[0], pl[1], pl[2], pl[3]);
}

__global__ void bias_pad_kernel(const float* __restrict__ b3) {
    int i = blockIdx.x * 256 + threadIdx.x;
    if (i < NPAD) gB3p[i] = (i < NOUT) ? b3[i] : 0.0f;
}

// ---------------- HMMA 2-pass fp16 GEMM --------------------------------------
// BM=128 BN=128 BK=32, 8 warps (4m x 2n), warp tile 32x64, 4-stage cp.async.
#define SROW 40                       // padded row stride (elems)
#define STG_B 30720                   // stage bytes: 3 * 128*40*2
#define NSTG 4
#define SMEM_GEMM (NSTG * STG_B + 512)

struct StageOff { enum { AH = 0, BH = 10240, BL = 20480 }; };

__device__ __forceinline__ void load_stage(
    uint32_t sb, int st, int kt, int tid,
    const __half* A, const __half* Bh, const __half* Bl,
    size_t m0, size_t n0, int K) {
    uint32_t so = sb + st * STG_B;
    int koff = kt * 32;
#pragma unroll
    for (int u = 0; u < 2; u++) {
        int i = tid + u * 256;
        int r = i >> 2;
        int kg = (i & 3) * 8;
        uint32_t d = so + (uint32_t)(r * SROW + kg) * 2;
        size_t ga = (m0 + r) * (size_t)K + koff + kg;
        size_t gb = (n0 + r) * (size_t)K + koff + kg;
        cpasync16(d + StageOff::AH, A + ga);
        cpasync16(d + StageOff::BH, Bh + gb);
        cpasync16(d + StageOff::BL, Bl + gb);
    }
    asm volatile("cp.async.commit_group;" ::: "memory");
}

template <bool RELU, bool FINAL>
__global__ __launch_bounds__(256, 1)
void hmma_gemm(const __half* __restrict__ A,
               const __half* __restrict__ Bh, const __half* __restrict__ Bl,
               const float* __restrict__ bias,
               __half* __restrict__ Oh, float* __restrict__ Op,
               int K, int Nld) {
    extern __shared__ __align__(128) char smem[];
    uint32_t sb = smem_u32(smem);
    float* bsm = (float*)(smem + NSTG * STG_B);

    int tid = threadIdx.x;
    int wid = tid >> 5, lane = tid & 31;
    int wm = wid & 3, wn = wid >> 2;
    size_t m0 = (size_t)blockIdx.y * 128;
    size_t n0 = (size_t)blockIdx.x * 128;
    int KT = K >> 5;

    if (tid < 128) bsm[tid] = bias[n0 + tid];

    float acc[2][8][4];
#pragma unroll
    for (int mi = 0; mi < 2; mi++)
#pragma unroll
        for (int nj = 0; nj < 8; nj++)
#pragma unroll
            for (int q = 0; q < 4; q++) acc[mi][nj][q] = 0.0f;

    int lrow = lane & 15;
    int lcol = (lane >> 4) * 8;
    uint32_t aBase = (uint32_t)((wm * 32 + lrow) * SROW + lcol) * 2;
    uint32_t bBase = (uint32_t)((wn * 64 + lrow) * SROW + lcol) * 2;

#pragma unroll
    for (int s = 0; s < NSTG - 1; s++)
        load_stage(sb, s, s, tid, A, Bh, Bl, m0, n0, K);

#pragma unroll 1
    for (int kt = 0; kt < KT; kt++) {
        asm volatile("cp.async.wait_group 2;" ::: "memory");
        __syncthreads();
        uint32_t so = sb + (kt & (NSTG - 1)) * STG_B;
#pragma unroll
        for (int k16 = 0; k16 < 2; k16++) {
            uint32_t kb = (uint32_t)(k16 * 16) * 2;
            uint32_t af[2][4];
#pragma unroll
            for (int mi = 0; mi < 2; mi++)
                ldm_x4(af[mi], so + aBase + (uint32_t)(mi * 16 * SROW) * 2 + kb + StageOff::AH);
#pragma unroll
            for (int nj = 0; nj < 4; nj++) {
                uint32_t bo = so + bBase + (uint32_t)(nj * 16 * SROW) * 2 + kb;
                uint32_t bh[4], bl[4];
                ldm_x4(bh, bo + StageOff::BH);
                ldm_x4(bl, bo + StageOff::BL);
#pragma unroll
                for (int mi = 0; mi < 2; mi++) {
                    float* c0 = acc[mi][nj * 2 + 0];
                    float* c1 = acc[mi][nj * 2 + 1];
                    mma_f16(c0, af[mi], bh[0], bh[2]);
                    mma_f16(c0, af[mi], bl[0], bl[2]);
                    mma_f16(c1, af[mi], bh[1], bh[3]);
                    mma_f16(c1, af[mi], bl[1], bl[3]);
                }
            }
        }
        __syncthreads();
        int nk = kt + NSTG - 1;
        if (nk < KT)
            load_stage(sb, nk & (NSTG - 1), nk, tid, A, Bh, Bl, m0, n0, K);
        else
            asm volatile("cp.async.commit_group;" ::: "memory");
    }

    // ---- epilogue ----
    int qrow = lane >> 2, qcol = (lane & 3) * 2;
#pragma unroll
    for (int mi = 0; mi < 2; mi++) {
#pragma unroll
        for (int nj = 0; nj < 8; nj++) {
            float* c = acc[mi][nj];
            int col = wn * 64 + nj * 8 + qcol;
            float bi0 = bsm[col], bi1 = bsm[col + 1];
#pragma unroll
            for (int h = 0; h < 2; h++) {
                size_t row = m0 + wm * 32 + mi * 16 + h * 8 + qrow;
                float v0 = c[h * 2 + 0] + bi0;
                float v1 = c[h * 2 + 1] + bi1;
                if (RELU) { v0 = fmaxf(v0, 0.0f); v1 = fmaxf(v1, 0.0f); }
                size_t o = row * (size_t)Nld + n0 + col;
                if (FINAL) {
                    *(float2*)(Op + o) = make_float2(v0, v1);
                } else {
                    *(uint32_t*)(Oh + o) = pack_h2(__float2half_rn(v0), __float2half_rn(v1));
                }
            }
        }
    }
}

// ---------------- rational-quadratic spline ----------------------------------
__device__ __forceinline__ float softplus_f(float x) {
    return fmaxf(x, 0.0f) + log1pf(expf(-fabsf(x)));
}

__global__ void spline_kernel(const float* __restrict__ x2g,
                              float* __restrict__ out) {
    const float SHIFT    = 0.5413248546129181f;   // log(e-1)
    const float SHIFT_DX = 5.1944681678044580f;   // log(exp(6-0.8)-1)
    __shared__ float red[4][2];

    int d = threadIdx.x;                          // 0..63
    int b = blockIdx.x * blockDim.y + threadIdx.y;

    const float* p = gP + (size_t)b * NPAD + d * 23;
    float pr[23];
#pragma unroll
    for (int i = 0; i < 23; i++) pr[i] = p[i];

    const float left = -3.0f;
    float dx = 0.8f + softplus_f(SHIFT_DX);
    float right = left + dx;
    float scale = right - left;

    float cw[9], ch[9], dv[9];
    {
        float m = pr[0];
#pragma unroll
        for (int i = 1; i < 8; i++) m = fmaxf(m, pr[i]);
        float e[8]; float s = 0.0f;
#pragma unroll
        for (int i = 0; i < 8; i++) { e[i] = expf(pr[i] - m); s += e[i]; }
        float inv = 1.0f / s;
        cw[0] = left;
        float cum = 0.0f;
#pragma unroll
        for (int i = 0; i < 8; i++) {
            cum += 0.1f + 0.2f * (e[i] * inv);
            cw[i + 1] = scale * cum + left;
        }
    }
    {
        float m = pr[8];
#pragma unroll
        for (int i = 1; i < 8; i++) m = fmaxf(m, pr[8 + i]);
        float e[8]; float s = 0.0f;
#pragma unroll
        for (int i = 0; i < 8; i++) { e[i] = expf(pr[8 + i] - m); s += e[i]; }
        float inv = 1.0f / s;
        ch[0] = left;
        float cum = 0.0f;
#pragma unroll
        for (int i = 0; i < 8; i++) {
            cum += 0.1f + 0.2f * (e[i] * inv);
            ch[i + 1] = scale * cum + left;
        }
    }
    dv[0] = 1.0f;
#pragma unroll
    for (int i = 0; i < 7; i++) dv[i + 1] = 0.001f + softplus_f(pr[16 + i] + SHIFT);
    dv[8] = 1.0f;

    float x = x2g[(size_t)b * 64 + d];

    int cnt = 0;
#pragma unroll
    for (int j = 0; j < 8; j++) cnt += (cw[j] <= x) ? 1 : 0;
    cnt += ((cw[8] + 1e-6f) <= x) ? 1 : 0;
    int idx = cnt - 1;
    idx = idx < 0 ? 0 : (idx > 7 ? 7 : idx);

    float x_k = cw[0], x_k1 = cw[1], y_k = ch[0], y_k1 = ch[1];
    float d0 = dv[0], d1 = dv[1];
#pragma unroll
    for (int j = 0; j < 8; j++) {
        if (j == idx) {
            x_k = cw[j]; x_k1 = cw[j + 1];
            y_k = ch[j]; y_k1 = ch[j + 1];
            d0 = dv[j];  d1 = dv[j + 1];
        }
    }
    float x_kd = x_k1 - x_k;
    float y_kd = y_k1 - y_k;
    float s_k = y_kd / x_kd;
    float xi = (x - x_k) / x_kd;
    float xi1m = xi * (1.0f - xi);
    float omxi = 1.0f - xi;
    float alpha = y_kd * (s_k * xi * xi + d0 * xi1m);
    float beta  = s_k + (d1 + d0 - 2.0f * s_k) * xi1m;
    float z_sp  = y_k + alpha / fmaxf(beta, 1e-8f);
    float num   = s_k * s_k * (d1 * xi * xi + 2.0f * s_k * xi1m + d0 * omxi * omxi);
    float ld_sp = logf(fmaxf(num, 1e-8f)) - 2.0f * logf(fmaxf(beta, 1e-8f));

    bool inside = (left <= x) && (x < right);
    float z  = inside ? z_sp : x;
    float ld = inside ? ld_sp : 0.0f;

    out[(size_t)b * 64 + d] = z;

#pragma unroll
    for (int off = 16; off > 0; off >>= 1)
        ld += __shfl_down_sync(0xffffffffu, ld, off);
    if ((d & 31) == 0) red[threadIdx.y][d >> 5] = ld;
    __syncthreads();
    if (d == 0)
        out[(size_t)BR * 64 + b] = red[threadIdx.y][0] + red[threadIdx.y][1];
}

// ---------------- launch -----------------------------------------------------
extern "C" void kernel_launch(void* const* d_in, const int* in_sizes, int n_in,
                              void* d_out, int out_size) {
    const float* x1    = (const float*)d_in[0];
    const float* x2    = (const float*)d_in[1];
    const float* ctx   = (const float*)d_in[2];
    const float* mask1 = (const float*)d_in[3];
    const float* W0    = (const float*)d_in[4];
    const float* b0    = (const float*)d_in[5];
    const float* W1    = (const float*)d_in[6];
    const float* b1    = (const float*)d_in[7];
    const float* W2    = (const float*)d_in[8];
    const float* b2    = (const float*)d_in[9];
    const float* W3    = (const float*)d_in[10];
    const float* b3    = (const float*)d_in[11];
    float* out = (float*)d_out;

    __half *a0, *h0, *h1;
    __half *w0h, *w0l, *w1h, *w1l, *w2h, *w2l, *w3h, *w3l;
    float *b3p, *pp;
    cudaGetSymbolAddress((void**)&a0, gA);
    cudaGetSymbolAddress((void**)&h0, gH0);
    cudaGetSymbolAddress((void**)&h1, gH1);
    cudaGetSymbolAddress((void**)&w0h, gW0h); cudaGetSymbolAddress((void**)&w0l, gW0l);
    cudaGetSymbolAddress((void**)&w1h, gW1h); cudaGetSymbolAddress((void**)&w1l, gW1l);
    cudaGetSymbolAddress((void**)&w2h, gW2h); cudaGetSymbolAddress((void**)&w2l, gW2l);
    cudaGetSymbolAddress((void**)&w3h, gW3h); cudaGetSymbolAddress((void**)&w3l, gW3l);
    cudaGetSymbolAddress((void**)&b3p, gB3p); cudaGetSymbolAddress((void**)&pp,  gP);

    cudaFuncSetAttribute(hmma_gemm<true, false>,
                         cudaFuncAttributeMaxDynamicSharedMemorySize, SMEM_GEMM);
    cudaFuncSetAttribute(hmma_gemm<false, true>,
                         cudaFuncAttributeMaxDynamicSharedMemorySize, SMEM_GEMM);

    concat_kernel<<<(BR * 32) / 256, 256>>>(x1, mask1, ctx);
    convert_w_kernel<<<((DIN / 8) * DFF) / 256, 256>>>(W0, w0h, w0l, DIN, DFF, DFF);
    convert_w_kernel<<<((DFF / 8) * DFF) / 256, 256>>>(W1, w1h, w1l, DFF, DFF, DFF);
    convert_w_kernel<<<((DFF / 8) * DFF) / 256, 256>>>(W2, w2h, w2l, DFF, DFF, DFF);
    convert_w_kernel<<<((DFF / 8) * NPAD) / 256, 256>>>(W3, w3h, w3l, DFF, NOUT, NPAD);
    bias_pad_kernel<<<(NPAD + 255) / 256, 256>>>(b3);

    dim3 g01(DFF / 128, BR / 128);
    hmma_gemm<true, false><<<g01, 256, SMEM_GEMM>>>(a0, w0h, w0l, b0, h0, nullptr, DIN, DFF);
    hmma_gemm<true, false><<<g01, 256, SMEM_GEMM>>>(h0, w1h, w1l, b1, h1, nullptr, DFF, DFF);
    hmma_gemm<true, false><<<g01, 256, SMEM_GEMM>>>(h1, w2h, w2l, b2, h0, nullptr, DFF, DFF);
    dim3 g3(NPAD / 128, BR / 128);
    hmma_gemm<false, true><<<g3, 256, SMEM_GEMM>>>(h0, w3h, w3l, b3p, nullptr, pp, DFF, NPAD);

    spline_kernel<<<BR / 4, dim3(64, 4)>>>(x2, out);
}

// round 5
// speedup vs baseline: 5.2068x; 1.8467x over previous
#include <cuda_runtime.h>
#include <cuda_fp16.h>
#include <math.h>
#include <stdint.h>

#define BR 65536
#define DFF 1024
#define DIN 256
#define NOUT 1472
#define NPAD 1536

// ---------------- static device scratch (allocation-guard safe) -------------
__device__ __align__(256) __half gA[(size_t)BR * DIN];
__device__ __align__(256) __half gH0[(size_t)BR * DFF];
__device__ __align__(256) __half gH1[(size_t)BR * DFF];
__device__ __align__(256) __half gW0[DFF * DIN];     // [N][K]
__device__ __align__(256) __half gW1[DFF * DFF];
__device__ __align__(256) __half gW2[DFF * DFF];
__device__ __align__(256) __half gW3[NPAD * DFF];
__device__ float gB3p[NPAD];
__device__ __align__(256) float gP[(size_t)BR * NPAD];   // params row-major

// ---------------- helpers ----------------------------------------------------
__device__ __forceinline__ uint32_t smem_u32(const void* p) {
    uint32_t a;
    asm("{ .reg .u64 t; cvta.to.shared.u64 t, %1; cvt.u32.u64 %0, t; }" : "=r"(a) : "l"(p));
    return a;
}
__device__ __forceinline__ void cpasync16(uint32_t dst, const void* src) {
    asm volatile("cp.async.cg.shared.global [%0], [%1], 16;" :: "r"(dst), "l"(src));
}
__device__ __forceinline__ void ldm_x4(uint32_t* r, uint32_t addr) {
    asm volatile("ldmatrix.sync.aligned.m8n8.x4.shared.b16 {%0,%1,%2,%3}, [%4];"
                 : "=r"(r[0]), "=r"(r[1]), "=r"(r[2]), "=r"(r[3]) : "r"(addr));
}
__device__ __forceinline__ void mma_f16(float* c, const uint32_t* a, uint32_t b0, uint32_t b1) {
    asm volatile("mma.sync.aligned.m16n8k16.row.col.f32.f16.f16.f32 "
                 "{%0,%1,%2,%3}, {%4,%5,%6,%7}, {%8,%9}, {%0,%1,%2,%3};"
                 : "+f"(c[0]), "+f"(c[1]), "+f"(c[2]), "+f"(c[3])
                 : "r"(a[0]), "r"(a[1]), "r"(a[2]), "r"(a[3]), "r"(b0), "r"(b1));
}
__device__ __forceinline__ uint32_t pack_h2(__half a, __half b) {
    __half2 t(a, b);
    return *reinterpret_cast<uint32_t*>(&t);
}

// ---------------- concat -> A [BR][256] fp16 ---------------------------------
__global__ void concat_kernel(const float* __restrict__ x1,
                              const float* __restrict__ m1,
                              const float* __restrict__ cx) {
    int t = blockIdx.x * 256 + threadIdx.x;
    int b = t >> 5;
    int jg = (t & 31) << 3;
    const float* src;
    if (jg < 64)       src = x1 + (size_t)b * 64 + jg;
    else if (jg < 128) src = m1 + (size_t)b * 64 + (jg - 64);
    else               src = cx + (size_t)b * 128 + (jg - 128);
    float4 u0 = *(const float4*)src;
    float4 u1 = *(const float4*)(src + 4);
    float v[8] = {u0.x, u0.y, u0.z, u0.w, u1.x, u1.y, u1.z, u1.w};
    uint32_t p[4];
#pragma unroll
    for (int g = 0; g < 4; g++)
        p[g] = pack_h2(__float2half_rn(v[g * 2]), __float2half_rn(v[g * 2 + 1]));
    *(uint4*)(gA + (size_t)b * DIN + jg) = make_uint4(p[0], p[1], p[2], p[3]);
}

// ---------------- weight transpose: W[K][N] -> fp16 [Npad][K] ----------------
__global__ void convert_w_kernel(const float* __restrict__ W,
                                 __half* __restrict__ Wt,
                                 int K, int N, int Npad) {
    int idx = blockIdx.x * 256 + threadIdx.x;          // (K/8)*Npad threads
    int kg = idx / Npad;
    int n = idx - kg * Npad;
    if (kg >= (K >> 3)) return;
    float v[8];
#pragma unroll
    for (int i = 0; i < 8; i++)
        v[i] = (n < N) ? W[(size_t)(kg * 8 + i) * N + n] : 0.0f;
    uint32_t p[4];
#pragma unroll
    for (int g = 0; g < 4; g++)
        p[g] = pack_h2(__float2half_rn(v[g * 2]), __float2half_rn(v[g * 2 + 1]));
    *(uint4*)(Wt + (size_t)n * K + kg * 8) = make_uint4(p[0], p[1], p[2], p[3]);
}

__global__ void bias_pad_kernel(const float* __restrict__ b3) {
    int i = blockIdx.x * 256 + threadIdx.x;
    if (i < NPAD) gB3p[i] = (i < NOUT) ? b3[i] : 0.0f;
}

// ---------------- HMMA fp16 GEMM ---------------------------------------------
// BM=128 BN=128 BK=32, 8 warps (4m x 2n), warp tile 32x64, 4-stage cp.async,
// 2 CTAs per SM for latency hiding.
#define SROW 40                       // padded row stride (elems)
#define STG_B 20480                   // stage bytes: 2 * 128*40*2
#define NSTG 4
#define SMEM_GEMM (NSTG * STG_B + 512)

struct StageOff { enum { AH = 0, BH = 10240 }; };

__device__ __forceinline__ void load_stage(
    uint32_t sb, int st, int kt, int tid,
    const __half* A, const __half* B,
    size_t m0, size_t n0, int K) {
    uint32_t so = sb + st * STG_B;
    int koff = kt * 32;
#pragma unroll
    for (int u = 0; u < 2; u++) {
        int i = tid + u * 256;
        int r = i >> 2;
        int kg = (i & 3) * 8;
        uint32_t d = so + (uint32_t)(r * SROW + kg) * 2;
        cpasync16(d + StageOff::AH, A + (m0 + r) * (size_t)K + koff + kg);
        cpasync16(d + StageOff::BH, B + (n0 + r) * (size_t)K + koff + kg);
    }
    asm volatile("cp.async.commit_group;" ::: "memory");
}

template <bool RELU, bool FINAL>
__global__ __launch_bounds__(256, 2)
void hmma_gemm(const __half* __restrict__ A, const __half* __restrict__ B,
               const float* __restrict__ bias,
               __half* __restrict__ Oh, float* __restrict__ Op,
               int K, int Nld) {
    extern __shared__ __align__(128) char smem[];
    uint32_t sb = smem_u32(smem);
    float* bsm = (float*)(smem + NSTG * STG_B);

    int tid = threadIdx.x;
    int wid = tid >> 5, lane = tid & 31;
    int wm = wid & 3, wn = wid >> 2;
    size_t m0 = (size_t)blockIdx.y * 128;
    size_t n0 = (size_t)blockIdx.x * 128;
    int KT = K >> 5;

    if (tid < 128) bsm[tid] = bias[n0 + tid];

    float acc[2][8][4];
#pragma unroll
    for (int mi = 0; mi < 2; mi++)
#pragma unroll
        for (int nj = 0; nj < 8; nj++)
#pragma unroll
            for (int q = 0; q < 4; q++) acc[mi][nj][q] = 0.0f;

    int lrow = lane & 15;
    int lcol = (lane >> 4) * 8;
    uint32_t aBase = (uint32_t)((wm * 32 + lrow) * SROW + lcol) * 2;
    uint32_t bBase = (uint32_t)((wn * 64 + lrow) * SROW + lcol) * 2;

#pragma unroll
    for (int s = 0; s < NSTG - 1; s++)
        load_stage(sb, s, s, tid, A, B, m0, n0, K);

#pragma unroll 1
    for (int kt = 0; kt < KT; kt++) {
        asm volatile("cp.async.wait_group 2;" ::: "memory");
        __syncthreads();
        uint32_t so = sb + (kt & (NSTG - 1)) * STG_B;
#pragma unroll
        for (int k16 = 0; k16 < 2; k16++) {
            uint32_t kb = (uint32_t)(k16 * 16) * 2;
            uint32_t af[2][4];
#pragma unroll
            for (int mi = 0; mi < 2; mi++)
                ldm_x4(af[mi], so + aBase + (uint32_t)(mi * 16 * SROW) * 2 + kb + StageOff::AH);
#pragma unroll
            for (int nj = 0; nj < 4; nj++) {
                uint32_t bf[4];
                ldm_x4(bf, so + bBase + (uint32_t)(nj * 16 * SROW) * 2 + kb + StageOff::BH);
#pragma unroll
                for (int mi = 0; mi < 2; mi++) {
                    mma_f16(acc[mi][nj * 2 + 0], af[mi], bf[0], bf[2]);
                    mma_f16(acc[mi][nj * 2 + 1], af[mi], bf[1], bf[3]);
                }
            }
        }
        __syncthreads();
        int nk = kt + NSTG - 1;
        if (nk < KT)
            load_stage(sb, nk & (NSTG - 1), nk, tid, A, B, m0, n0, K);
        else
            asm volatile("cp.async.commit_group;" ::: "memory");
    }

    // ---- epilogue ----
    int qrow = lane >> 2, qcol = (lane & 3) * 2;
#pragma unroll
    for (int mi = 0; mi < 2; mi++) {
#pragma unroll
        for (int nj = 0; nj < 8; nj++) {
            float* c = acc[mi][nj];
            int col = wn * 64 + nj * 8 + qcol;
            float bi0 = bsm[col], bi1 = bsm[col + 1];
#pragma unroll
            for (int h = 0; h < 2; h++) {
                size_t row = m0 + wm * 32 + mi * 16 + h * 8 + qrow;
                float v0 = c[h * 2 + 0] + bi0;
                float v1 = c[h * 2 + 1] + bi1;
                if (RELU) { v0 = fmaxf(v0, 0.0f); v1 = fmaxf(v1, 0.0f); }
                size_t o = row * (size_t)Nld + n0 + col;
                if (FINAL) {
                    *(float2*)(Op + o) = make_float2(v0, v1);
                } else {
                    *(uint32_t*)(Oh + o) = pack_h2(__float2half_rn(v0), __float2half_rn(v1));
                }
            }
        }
    }
}

// ---------------- rational-quadratic spline ----------------------------------
__device__ __forceinline__ float softplus_f(float x) {
    return fmaxf(x, 0.0f) + log1pf(expf(-fabsf(x)));
}

__global__ void spline_kernel(const float* __restrict__ x2g,
                              float* __restrict__ out) {
    const float SHIFT    = 0.5413248546129181f;   // log(e-1)
    const float SHIFT_DX = 5.1944681678044580f;   // log(exp(6-0.8)-1)
    __shared__ float red[4][2];

    int d = threadIdx.x;                          // 0..63
    int b = blockIdx.x * blockDim.y + threadIdx.y;

    const float* p = gP + (size_t)b * NPAD + d * 23;
    float pr[23];
#pragma unroll
    for (int i = 0; i < 23; i++) pr[i] = p[i];

    const float left = -3.0f;
    float dx = 0.8f + softplus_f(SHIFT_DX);
    float right = left + dx;
    float scale = right - left;

    float cw[9], ch[9], dv[9];
    {
        float m = pr[0];
#pragma unroll
        for (int i = 1; i < 8; i++) m = fmaxf(m, pr[i]);
        float e[8]; float s = 0.0f;
#pragma unroll
        for (int i = 0; i < 8; i++) { e[i] = expf(pr[i] - m); s += e[i]; }
        float inv = 1.0f / s;
        cw[0] = left;
        float cum = 0.0f;
#pragma unroll
        for (int i = 0; i < 8; i++) {
            cum += 0.1f + 0.2f * (e[i] * inv);
            cw[i + 1] = scale * cum + left;
        }
    }
    {
        float m = pr[8];
#pragma unroll
        for (int i = 1; i < 8; i++) m = fmaxf(m, pr[8 + i]);
        float e[8]; float s = 0.0f;
#pragma unroll
        for (int i = 0; i < 8; i++) { e[i] = expf(pr[8 + i] - m); s += e[i]; }
        float inv = 1.0f / s;
        ch[0] = left;
        float cum = 0.0f;
#pragma unroll
        for (int i = 0; i < 8; i++) {
            cum += 0.1f + 0.2f * (e[i] * inv);
            ch[i + 1] = scale * cum + left;
        }
    }
    dv[0] = 1.0f;
#pragma unroll
    for (int i = 0; i < 7; i++) dv[i + 1] = 0.001f + softplus_f(pr[16 + i] + SHIFT);
    dv[8] = 1.0f;

    float x = x2g[(size_t)b * 64 + d];

    int cnt = 0;
#pragma unroll
    for (int j = 0; j < 8; j++) cnt += (cw[j] <= x) ? 1 : 0;
    cnt += ((cw[8] + 1e-6f) <= x) ? 1 : 0;
    int idx = cnt - 1;
    idx = idx < 0 ? 0 : (idx > 7 ? 7 : idx);

    float x_k = cw[0], x_k1 = cw[1], y_k = ch[0], y_k1 = ch[1];
    float d0 = dv[0], d1 = dv[1];
#pragma unroll
    for (int j = 0; j < 8; j++) {
        if (j == idx) {
            x_k = cw[j]; x_k1 = cw[j + 1];
            y_k = ch[j]; y_k1 = ch[j + 1];
            d0 = dv[j];  d1 = dv[j + 1];
        }
    }
    float x_kd = x_k1 - x_k;
    float y_kd = y_k1 - y_k;
    float s_k = y_kd / x_kd;
    float xi = (x - x_k) / x_kd;
    float xi1m = xi * (1.0f - xi);
    float omxi = 1.0f - xi;
    float alpha = y_kd * (s_k * xi * xi + d0 * xi1m);
    float beta  = s_k + (d1 + d0 - 2.0f * s_k) * xi1m;
    float z_sp  = y_k + alpha / fmaxf(beta, 1e-8f);
    float num   = s_k * s_k * (d1 * xi * xi + 2.0f * s_k * xi1m + d0 * omxi * omxi);
    float ld_sp = logf(fmaxf(num, 1e-8f)) - 2.0f * logf(fmaxf(beta, 1e-8f));

    bool inside = (left <= x) && (x < right);
    float z  = inside ? z_sp : x;
    float ld = inside ? ld_sp : 0.0f;

    out[(size_t)b * 64 + d] = z;

#pragma unroll
    for (int off = 16; off > 0; off >>= 1)
        ld += __shfl_down_sync(0xffffffffu, ld, off);
    if ((d & 31) == 0) red[threadIdx.y][d >> 5] = ld;
    __syncthreads();
    if (d == 0)
        out[(size_t)BR * 64 + b] = red[threadIdx.y][0] + red[threadIdx.y][1];
}

// ---------------- launch -----------------------------------------------------
extern "C" void kernel_launch(void* const* d_in, const int* in_sizes, int n_in,
                              void* d_out, int out_size) {
    const float* x1    = (const float*)d_in[0];
    const float* x2    = (const float*)d_in[1];
    const float* ctx   = (const float*)d_in[2];
    const float* mask1 = (const float*)d_in[3];
    const float* W0    = (const float*)d_in[4];
    const float* b0    = (const float*)d_in[5];
    const float* W1    = (const float*)d_in[6];
    const float* b1    = (const float*)d_in[7];
    const float* W2    = (const float*)d_in[8];
    const float* b2    = (const float*)d_in[9];
    const float* W3    = (const float*)d_in[10];
    const float* b3    = (const float*)d_in[11];
    float* out = (float*)d_out;

    __half *a0, *h0, *h1, *w0, *w1, *w2, *w3;
    float *b3p, *pp;
    cudaGetSymbolAddress((void**)&a0, gA);
    cudaGetSymbolAddress((void**)&h0, gH0);
    cudaGetSymbolAddress((void**)&h1, gH1);
    cudaGetSymbolAddress((void**)&w0, gW0);
    cudaGetSymbolAddress((void**)&w1, gW1);
    cudaGetSymbolAddress((void**)&w2, gW2);
    cudaGetSymbolAddress((void**)&w3, gW3);
    cudaGetSymbolAddress((void**)&b3p, gB3p);
    cudaGetSymbolAddress((void**)&pp,  gP);

    cudaFuncSetAttribute(hmma_gemm<true, false>,
                         cudaFuncAttributeMaxDynamicSharedMemorySize, SMEM_GEMM);
    cudaFuncSetAttribute(hmma_gemm<false, true>,
                         cudaFuncAttributeMaxDynamicSharedMemorySize, SMEM_GEMM);

    concat_kernel<<<(BR * 32) / 256, 256>>>(x1, mask1, ctx);
    convert_w_kernel<<<((DIN / 8) * DFF) / 256, 256>>>(W0, w0, DIN, DFF, DFF);
    convert_w_kernel<<<((DFF / 8) * DFF) / 256, 256>>>(W1, w1, DFF, DFF, DFF);
    convert_w_kernel<<<((DFF / 8) * DFF) / 256, 256>>>(W2, w2, DFF, DFF, DFF);
    convert_w_kernel<<<((DFF / 8) * NPAD) / 256, 256>>>(W3, w3, DFF, NOUT, NPAD);
    bias_pad_kernel<<<(NPAD + 255) / 256, 256>>>(b3);

    dim3 g01(DFF / 128, BR / 128);
    hmma_gemm<true, false><<<g01, 256, SMEM_GEMM>>>(a0, w0, b0, h0, nullptr, DIN, DFF);
    hmma_gemm<true, false><<<g01, 256, SMEM_GEMM>>>(h0, w1, b1, h1, nullptr, DFF, DFF);
    hmma_gemm<true, false><<<g01, 256, SMEM_GEMM>>>(h1, w2, b2, h0, nullptr, DFF, DFF);
    dim3 g3(NPAD / 128, BR / 128);
    hmma_gemm<false, true><<<g3, 256, SMEM_GEMM>>>(h0, w3, b3p, nullptr, pp, DFF, NPAD);

    spline_kernel<<<BR / 4, dim3(64, 4)>>>(x2, out);
}